// round 3
// baseline (speedup 1.0000x reference)
#include <cuda_runtime.h>

// HopfOscillatorModule, round 3: lane = oscillator, one row per warp-iteration,
// f32x2 FMAs packed over the j (neighbor) dimension:
//   accP1 = (sum_{even j} A_ij x_j , sum_{odd j} A_ij x_j)   etc.
// Coefficient pairs (A_{i,2k},A_{i,2k+1}) live directly in 64-bit register
// pairs (loaded once from global, no dup MOVs). x/y pairs come from a
// contiguous per-warp shared array via one broadcast LDS.64 each.
// Double-buffered xy + software prefetch of the next row's loads.

#define NOSC 32
#define TWO_PI 6.283185307179586f
#define CTA_THREADS 128
#define WARPS_PER_CTA (CTA_THREADS / 32)
#define NUM_CTAS 1024

typedef unsigned long long u64;

__device__ float g_A[NOSC * NOSC];   // w*cos(phi), zero-diag, row-major [i][j]
__device__ float g_B[NOSC * NOSC];   // w*sin(phi), zero-diag
__device__ float4 g_par[NOSC];       // (K0, K1, K2, two_pi_v)

__device__ __forceinline__ float sigmoidf_(float x) { return 1.0f / (1.0f + expf(-x)); }

__global__ void hopf_setup_kernel(const float* __restrict__ v, const float* __restrict__ b,
                                  const float* __restrict__ c, const float* __restrict__ w,
                                  const float* __restrict__ phi)
{
    int k = threadIdx.x;  // flat index into 32x32 zero-diag matrices
    float A = 0.0f, Bc = 0.0f;
    if (k < 1023) {
        // _zero_diag: z = concat([zeros(31,1), P],1).ravel() ++ [0] -> (32,32)
        int t = k / 33, pos = k % 33;
        if (pos != 0) {
            float wa = sigmoidf_(w[t * 32 + pos - 1]);            // W_MAX = 1
            float pa = TWO_PI * sigmoidf_(phi[t * 32 + pos - 1]);
            float sp, cp;
            sincosf(pa, &sp, &cp);
            A = wa * cp;
            Bc = wa * sp;
        }
    }
    g_A[k] = A;
    g_B[k] = Bc;
    if (k < NOSC) {
        float va = 5.0f * sigmoidf_(v[k]);
        float ba = 2.0f * sigmoidf_(b[k]);
        float ca = 10.0f * sigmoidf_(c[k]);
        float K1 = 0.25f * ca * ca;
        g_par[k] = make_float4(K1 * ba, K1, ca, TWO_PI * va);  // r_d_dot = K0 - K1*r - K2*rd
    }
}

// ---------------- packed f32x2 helpers ----------------
__device__ __forceinline__ void ffma2(u64& d, u64 a, u64 b) {
    asm("fma.rn.f32x2 %0, %1, %2, %0;" : "+l"(d) : "l"(a), "l"(b));
}
__device__ __forceinline__ u64 sub2(u64 a, u64 b) {
    u64 r;
    asm("sub.rn.f32x2 %0, %1, %2;" : "=l"(r) : "l"(a), "l"(b));
    return r;
}
__device__ __forceinline__ u64 add2(u64 a, u64 b) {
    u64 r;
    asm("add.rn.f32x2 %0, %1, %2;" : "=l"(r) : "l"(a), "l"(b));
    return r;
}
__device__ __forceinline__ void upk2(u64 v, float& lo, float& hi) {
    asm("mov.b64 {%0, %1}, %2;" : "=f"(lo), "=f"(hi) : "l"(v));
}

__global__ __launch_bounds__(CTA_THREADS) void hopf_kernel(const float* __restrict__ in,
                                                           float* __restrict__ out,
                                                           int nrows, int nwarps_total)
{
    __shared__ __align__(16) float sX[2][WARPS_PER_CTA][NOSC];
    __shared__ __align__(16) float sY[2][WARPS_PER_CTA][NOSC];

    int tid = threadIdx.x;
    int lane = tid & 31;
    int wid = tid >> 5;

    // Per-lane coefficient row as 16 packed (even,odd) 64-bit pairs each.
    u64 PA[16], PB[16];
    {
        const u64* ga = (const u64*)(g_A + lane * NOSC);
        const u64* gb = (const u64*)(g_B + lane * NOSC);
#pragma unroll
        for (int jp = 0; jp < 16; jp++) {
            PA[jp] = ga[jp];
            PB[jp] = gb[jp];
        }
    }
    float4 par = g_par[lane];  // (K0, K1, K2, two_pi_v)

    int gw = blockIdx.x * WARPS_PER_CTA + wid;
    int row = gw;
    int pb = 0;

    float psi = 0.f, rr = 0.f, rd = 0.f;
    if (row < nrows) {
        const float* rp = in + (size_t)row * 96;
        psi = rp[lane];
        rr = rp[32 + lane];
        rd = rp[64 + lane];
    }

    while (row < nrows) {
        int nxt = row + nwarps_total;

        float s, c;
        __sincosf(psi, &s, &c);
        sX[pb][wid][lane] = rr * s;
        sY[pb][wid][lane] = rr * c;

        // Prefetch next row (hidden behind the j-loop).
        float npsi = 0.f, nrr = 0.f, nrd = 0.f;
        if (nxt < nrows) {
            const float* np = in + (size_t)nxt * 96;
            npsi = np[lane];
            nrr = np[32 + lane];
            nrd = np[64 + lane];
        }
        __syncwarp();

        const u64* bx = (const u64*)sX[pb][wid];
        const u64* by = (const u64*)sY[pb][wid];
        u64 P1 = 0ull, P2 = 0ull, Q1 = 0ull, Q2 = 0ull;
#pragma unroll
        for (int jp = 0; jp < 16; jp++) {
            u64 xp = bx[jp];   // LDS.64 broadcast: (x_{2jp}, x_{2jp+1})
            u64 yp = by[jp];
            ffma2(P1, PA[jp], xp);
            ffma2(P2, PB[jp], yp);
            ffma2(Q1, PB[jp], xp);
            ffma2(Q2, PA[jp], yp);
        }

        u64 Ppk = sub2(P1, P2);   // packed (even,odd) of P = A.x - B.y
        u64 Qpk = add2(Q1, Q2);   // packed (even,odd) of Q = B.x + A.y
        float pl, ph, ql, qh;
        upk2(Ppk, pl, ph);
        upk2(Qpk, ql, qh);
        float P = pl + ph;
        float Q = ql + qh;

        float psidot = fmaf(c, P, fmaf(-s, Q, par.w));
        float f = fmaf(-par.z, rd, fmaf(-par.y, rr, par.x));

        float* o = out + (size_t)row * 96;
        o[lane] = psidot;
        o[32 + lane] = rd;
        o[64 + lane] = f;

        psi = npsi;
        rr = nrr;
        rd = nrd;
        row = nxt;
        pb ^= 1;
    }
}

extern "C" void kernel_launch(void* const* d_in, const int* in_sizes, int n_in,
                              void* d_out, int out_size)
{
    const float* states = (const float*)d_in[0];
    const float* v = (const float*)d_in[1];
    const float* b = (const float*)d_in[2];
    const float* c = (const float*)d_in[3];
    const float* w = (const float*)d_in[4];
    const float* phi = (const float*)d_in[5];
    int nrows = in_sizes[0] / 96;

    hopf_setup_kernel<<<1, 1024>>>(v, b, c, w, phi);

    int nwarps_total = NUM_CTAS * WARPS_PER_CTA;
    hopf_kernel<<<NUM_CTAS, CTA_THREADS>>>(states, (float*)d_out, nrows, nwarps_total);
}